// round 1
// baseline (speedup 1.0000x reference)
#include <cuda_runtime.h>

#define B 8
#define E 256
#define T 4096
#define H 8
#define GC 32   // E/H channels per group
#define KW 3

#define BM 64
#define BN 64
#define QS 260  // padded row stride (floats) for 256-wide tiles
#define PS 65

#define CTT 256 // conv time-tile

// Scratch (B*T*E floats = 33.5 MB each)
__device__ float g_q[B * T * E];
__device__ float g_k[B * T * E];
__device__ float g_v[B * T * E];
__device__ float g_o[B * T * E];

// ---------------------------------------------------------------------------
// Kernel 1: fused grouped conv1d for q, k, v.  Output layout: [B, T, E].
// Block: (T-tile, group, batch); 256 threads, one t-position per thread.
// ---------------------------------------------------------------------------
__global__ __launch_bounds__(256) void conv_qkv_kernel(
    const float* __restrict__ x,
    const float* __restrict__ wq, const float* __restrict__ bq,
    const float* __restrict__ wk, const float* __restrict__ bk,
    const float* __restrict__ wv, const float* __restrict__ bv)
{
    extern __shared__ float sm[];
    float* sx = sm;                       // GC * (CTT+2) = 8256
    float* sw = sx + GC * (CTT + 2);      // 3 * 3072 = 9216
    float* st = sw + 3 * GC * GC * KW;    // 256 * 33 = 8448 (output staging)

    const int tid = threadIdx.x;
    const int b = blockIdx.z, g = blockIdx.y;
    const int t0 = blockIdx.x * CTT;

    // Load this group's weights for all 3 projections into smem.
    const int gw = g * GC * GC * KW;  // 3072
    for (int i = tid; i < GC * GC * KW; i += 256) {
        sw[i]        = wq[gw + i];
        sw[3072 + i] = wk[gw + i];
        sw[6144 + i] = wv[gw + i];
    }
    // Load x tile (32 channels x CTT+2 halo columns), zero-padded.
    for (int i = tid; i < GC * (CTT + 2); i += 256) {
        int ic = i / (CTT + 2), tt = i % (CTT + 2);
        int t = t0 + tt - 1;
        sx[i] = (t >= 0 && t < T) ? x[((size_t)b * E + g * GC + ic) * T + t] : 0.f;
    }
    __syncthreads();

    float aq[GC], ak[GC], av[GC];
#pragma unroll
    for (int oc = 0; oc < GC; oc++) { aq[oc] = 0.f; ak[oc] = 0.f; av[oc] = 0.f; }

    const int p = tid;  // this thread's t position within the tile
    for (int ic = 0; ic < GC; ic++) {
        float x0 = sx[ic * (CTT + 2) + p];
        float x1 = sx[ic * (CTT + 2) + p + 1];
        float x2 = sx[ic * (CTT + 2) + p + 2];
#pragma unroll
        for (int oc = 0; oc < GC; oc++) {
            int wb = (oc * GC + ic) * KW;
            aq[oc] += x0 * sw[wb] + x1 * sw[wb + 1] + x2 * sw[wb + 2];
            ak[oc] += x0 * sw[3072 + wb] + x1 * sw[3072 + wb + 1] + x2 * sw[3072 + wb + 2];
            av[oc] += x0 * sw[6144 + wb] + x1 * sw[6144 + wb + 1] + x2 * sw[6144 + wb + 2];
        }
    }

    // Coalesced output via smem transpose staging. Layout [t][c] (=[B,T,E]).
    const size_t obase = ((size_t)b * T + t0) * E + g * GC;

#pragma unroll
    for (int oc = 0; oc < GC; oc++) st[p * 33 + oc] = aq[oc] + bq[g * GC + oc];
    __syncthreads();
    for (int i = tid; i < CTT * GC; i += 256) {
        int t = i >> 5, oc = i & 31;
        g_q[obase + (size_t)t * E + oc] = st[t * 33 + oc];
    }
    __syncthreads();

#pragma unroll
    for (int oc = 0; oc < GC; oc++) st[p * 33 + oc] = ak[oc] + bk[g * GC + oc];
    __syncthreads();
    for (int i = tid; i < CTT * GC; i += 256) {
        int t = i >> 5, oc = i & 31;
        g_k[obase + (size_t)t * E + oc] = st[t * 33 + oc];
    }
    __syncthreads();

#pragma unroll
    for (int oc = 0; oc < GC; oc++) st[p * 33 + oc] = av[oc] + bv[g * GC + oc];
    __syncthreads();
    for (int i = tid; i < CTT * GC; i += 256) {
        int t = i >> 5, oc = i & 31;
        g_v[obase + (size_t)t * E + oc] = st[t * 33 + oc];
    }
}

// ---------------------------------------------------------------------------
// Kernel 2: flash attention, fp32, full (non-causal) softmax over T=4096.
// Block handles BM=64 query rows; loops over 64 KV tiles of BN=64.
// Thread (ty=tid/16, tx=tid%16) owns S rows {ty+16i}, cols {tx+16j},
// and O rows {ty+16i}, d-cols {q*64 + tx*4 .. +3}.
// ---------------------------------------------------------------------------
__global__ __launch_bounds__(256, 1) void attn_kernel()
{
    extern __shared__ float sm[];
    float* sQ = sm;                 // BM * QS
    float* sK = sQ + BM * QS;       // BN * QS
    float* sV = sK + BN * QS;       // BN * QS
    float* sP = sV + BN * QS;       // BM * PS

    const int tid = threadIdx.x;
    const int tx = tid & 15, ty = tid >> 4;
    const int b = blockIdx.y;
    const int q0 = blockIdx.x * BM;
    const float scale = 0.0625f;  // 1/sqrt(256)

    // Load Q tile
    const float* qg = g_q + ((size_t)b * T + q0) * E;
    for (int i = tid; i < BM * 64; i += 256) {
        int r = i >> 6, d4 = i & 63;
        *(float4*)&sQ[r * QS + d4 * 4] = *(const float4*)&qg[r * E + d4 * 4];
    }

    float m[4], l[4];
    float4 o[4][4];
#pragma unroll
    for (int i = 0; i < 4; i++) {
        m[i] = -1e30f; l[i] = 0.f;
#pragma unroll
        for (int q = 0; q < 4; q++) o[i][q] = make_float4(0.f, 0.f, 0.f, 0.f);
    }

    for (int kt = 0; kt < T / BN; kt++) {
        __syncthreads();   // previous iteration's PV reads done
        const float* kg = g_k + ((size_t)b * T + kt * BN) * E;
        const float* vg = g_v + ((size_t)b * T + kt * BN) * E;
        for (int i = tid; i < BN * 64; i += 256) {
            int r = i >> 6, d4 = i & 63;
            *(float4*)&sK[r * QS + d4 * 4] = *(const float4*)&kg[r * E + d4 * 4];
            *(float4*)&sV[r * QS + d4 * 4] = *(const float4*)&vg[r * E + d4 * 4];
        }
        __syncthreads();

        // ---- S = Q Kᵀ (4x4 micro-tile per thread) ----
        float s[4][4];
#pragma unroll
        for (int i = 0; i < 4; i++)
#pragma unroll
            for (int j = 0; j < 4; j++) s[i][j] = 0.f;

#pragma unroll 4
        for (int d4 = 0; d4 < 64; d4++) {
            float4 qv[4], kv[4];
#pragma unroll
            for (int i = 0; i < 4; i++) qv[i] = *(const float4*)&sQ[(ty + 16 * i) * QS + d4 * 4];
#pragma unroll
            for (int j = 0; j < 4; j++) kv[j] = *(const float4*)&sK[(tx + 16 * j) * QS + d4 * 4];
#pragma unroll
            for (int i = 0; i < 4; i++)
#pragma unroll
                for (int j = 0; j < 4; j++) {
                    s[i][j] += qv[i].x * kv[j].x;
                    s[i][j] += qv[i].y * kv[j].y;
                    s[i][j] += qv[i].z * kv[j].z;
                    s[i][j] += qv[i].w * kv[j].w;
                }
        }

        // ---- online softmax update ----
#pragma unroll
        for (int i = 0; i < 4; i++) {
#pragma unroll
            for (int j = 0; j < 4; j++) s[i][j] *= scale;
            float tm = fmaxf(fmaxf(s[i][0], s[i][1]), fmaxf(s[i][2], s[i][3]));
#pragma unroll
            for (int off = 1; off < 16; off <<= 1)
                tm = fmaxf(tm, __shfl_xor_sync(0xffffffffu, tm, off));
            float mn = fmaxf(m[i], tm);
            float corr = __expf(m[i] - mn);
            float rs = 0.f;
#pragma unroll
            for (int j = 0; j < 4; j++) {
                s[i][j] = __expf(s[i][j] - mn);
                rs += s[i][j];
            }
#pragma unroll
            for (int off = 1; off < 16; off <<= 1)
                rs += __shfl_xor_sync(0xffffffffu, rs, off);
            l[i] = l[i] * corr + rs;
            m[i] = mn;
#pragma unroll
            for (int q = 0; q < 4; q++) {
                o[i][q].x *= corr; o[i][q].y *= corr;
                o[i][q].z *= corr; o[i][q].w *= corr;
            }
#pragma unroll
            for (int j = 0; j < 4; j++)
                sP[(ty + 16 * i) * PS + tx + 16 * j] = s[i][j];
        }
        __syncthreads();

        // ---- O += P V ----
#pragma unroll 4
        for (int c = 0; c < BN; c++) {
            float pv[4];
#pragma unroll
            for (int i = 0; i < 4; i++) pv[i] = sP[(ty + 16 * i) * PS + c];
            float4 v4[4];
#pragma unroll
            for (int q = 0; q < 4; q++) v4[q] = *(const float4*)&sV[c * QS + q * 64 + tx * 4];
#pragma unroll
            for (int i = 0; i < 4; i++)
#pragma unroll
                for (int q = 0; q < 4; q++) {
                    o[i][q].x += pv[i] * v4[q].x;
                    o[i][q].y += pv[i] * v4[q].y;
                    o[i][q].z += pv[i] * v4[q].z;
                    o[i][q].w += pv[i] * v4[q].w;
                }
        }
    }

    // Epilogue: normalize and store [B,T,E]
    float* og = g_o + ((size_t)b * T + q0) * E;
#pragma unroll
    for (int i = 0; i < 4; i++) {
        float inv = 1.f / l[i];
#pragma unroll
        for (int q = 0; q < 4; q++) {
            float4 w = o[i][q];
            w.x *= inv; w.y *= inv; w.z *= inv; w.w *= inv;
            *(float4*)&og[(size_t)(ty + 16 * i) * E + q * 64 + tx * 4] = w;
        }
    }
}

// ---------------------------------------------------------------------------
// Kernel 3: fc_out  — out[r, o] = sum_e g_o[r, e] * w_fc[o, e] + b_fc[o]
// 64x64 tile per block over [B*T, E].
// ---------------------------------------------------------------------------
#define FCS 68
__global__ __launch_bounds__(256) void fc_kernel(
    const float* __restrict__ wfc, const float* __restrict__ bfc,
    float* __restrict__ out)
{
    extern __shared__ float sm[];
    float* sA = sm;               // 64 * FCS
    float* sW = sA + 64 * FCS;    // 64 * FCS

    const int tid = threadIdx.x;
    const int tx = tid & 15, ty = tid >> 4;
    const int r0 = blockIdx.y * 64, c0 = blockIdx.x * 64;

    float acc[4][4];
#pragma unroll
    for (int i = 0; i < 4; i++)
#pragma unroll
        for (int j = 0; j < 4; j++) acc[i][j] = 0.f;

    for (int e0 = 0; e0 < E; e0 += 64) {
        __syncthreads();
        for (int i = tid; i < 64 * 16; i += 256) {
            int r = i >> 4, e4 = i & 15;
            *(float4*)&sA[r * FCS + e4 * 4] =
                *(const float4*)&g_o[(size_t)(r0 + r) * E + e0 + e4 * 4];
            *(float4*)&sW[r * FCS + e4 * 4] =
                *(const float4*)&wfc[(size_t)(c0 + r) * E + e0 + e4 * 4];
        }
        __syncthreads();
#pragma unroll
        for (int e4 = 0; e4 < 16; e4++) {
            float4 a4[4], w4[4];
#pragma unroll
            for (int i = 0; i < 4; i++) a4[i] = *(const float4*)&sA[(ty + 16 * i) * FCS + e4 * 4];
#pragma unroll
            for (int j = 0; j < 4; j++) w4[j] = *(const float4*)&sW[(tx + 16 * j) * FCS + e4 * 4];
#pragma unroll
            for (int i = 0; i < 4; i++)
#pragma unroll
                for (int j = 0; j < 4; j++) {
                    acc[i][j] += a4[i].x * w4[j].x;
                    acc[i][j] += a4[i].y * w4[j].y;
                    acc[i][j] += a4[i].z * w4[j].z;
                    acc[i][j] += a4[i].w * w4[j].w;
                }
        }
    }

#pragma unroll
    for (int j = 0; j < 4; j++) {
        float bias = bfc[c0 + tx + 16 * j];
#pragma unroll
        for (int i = 0; i < 4; i++)
            out[(size_t)(r0 + ty + 16 * i) * E + c0 + tx + 16 * j] = acc[i][j] + bias;
    }
}

// ---------------------------------------------------------------------------

extern "C" void kernel_launch(void* const* d_in, const int* in_sizes, int n_in,
                              void* d_out, int out_size)
{
    const float* x   = (const float*)d_in[0];
    const float* wq  = (const float*)d_in[1];
    const float* bq  = (const float*)d_in[2];
    const float* wk  = (const float*)d_in[3];
    const float* bk  = (const float*)d_in[4];
    const float* wv  = (const float*)d_in[5];
    const float* bv  = (const float*)d_in[6];
    const float* wfc = (const float*)d_in[7];
    const float* bfc = (const float*)d_in[8];
    float* out = (float*)d_out;

    const int conv_smem = (GC * (CTT + 2) + 3 * GC * GC * KW + 256 * 33) * 4;
    const int attn_smem = (3 * BM * QS + BM * PS) * 4;   // 216320 B
    const int fc_smem   = 2 * 64 * FCS * 4;

    cudaFuncSetAttribute(conv_qkv_kernel, cudaFuncAttributeMaxDynamicSharedMemorySize, conv_smem);
    cudaFuncSetAttribute(attn_kernel, cudaFuncAttributeMaxDynamicSharedMemorySize, attn_smem);

    conv_qkv_kernel<<<dim3(T / CTT, H, B), 256, conv_smem>>>(x, wq, bq, wk, bk, wv, bv);
    attn_kernel<<<dim3(T / BM, B), 256, attn_smem>>>();
    fc_kernel<<<dim3(E / 64, (B * T) / 64), 256, fc_smem>>>(wfc, bfc, out);
}